// round 10
// baseline (speedup 1.0000x reference)
#include <cuda_runtime.h>
#include <math.h>
#include <stdint.h>

#define C_DIM 512
#define CF    256      // cond features
#define NH    8
#define DH    64
#define NTOK  4096     // N*H*W = 4*32*32
#define HH    32
#define WWID  32
#define KSZ   7
#define WIN   49
#define EPSF  1e-6f

// GEMM tiling
#define BK        32
#define AP        36            // A smem row stride (words): bank = 4r+c, conflict-free
#define BP        136           // B smem k-row stride (words): bank = 8c+r, conflict-free
#define A_WORDS   (128 * AP)    // 4608
#define B_WORDS   (BK * BP)     // 4352
#define STG_WORDS (A_WORDS + B_WORDS)
#define NSTAGE    3
#define GEMM_SMEM (NSTAGE * STG_WORDS * 4)   // 107520 bytes

// attention tiling: 4x8 token tile (32 tokens), window union <= 10x14
#define ATH       4
#define ATW       8
#define NTOK_T    32            // tokens per block
#define SPAN_H    10
#define SPAN_W    14
#define KVROWS    (SPAN_H * SPAN_W)   // 140
#define KVSTRIDE  68            // padded row stride (words) for K/V smem rows
#define ATTN_SMEM ((KVROWS * KVSTRIDE * 2 + NTOK_T * KVSTRIDE + NTOK_T * 52 + NTOK_T) * 4)

// fused norm smem: x tile [512][33] + reductions
#define NORM_SMEM ((C_DIM * 33 + 8 * 33 + 32) * 4)

// ---------------- scratch (static device globals; no allocations) ------------
__device__ float g_s[C_DIM];
__device__ float g_xn[NTOK * C_DIM];          // 8 MB
__device__ float g_qkv[NTOK * 3 * C_DIM];     // 24 MB  (q|k|v each 512 cols)
__device__ float g_o[NTOK * C_DIM];           // 8 MB

// ---------------- s = cond @ norm_w + 1 --------------------------------------
__global__ void nsab_s_kernel(const float* __restrict__ cond,
                              const float* __restrict__ norm_w) {
    int c = blockIdx.x * blockDim.x + threadIdx.x;
    if (c >= C_DIM) return;
    float acc = 1.0f;
#pragma unroll 8
    for (int k = 0; k < CF; k++) acc += cond[k] * norm_w[k * C_DIM + c];
    g_s[c] = acc;
}

// ---------------- fused RMS-norm + transpose (C,tok)->(tok,C) ----------------
__global__ __launch_bounds__(256) void nsab_norm_fused(const float* __restrict__ x) {
    extern __shared__ float smf[];
    float* t    = smf;                       // [512][33]
    float* red  = smf + C_DIM * 33;          // [8][33]
    float* rsh  = red + 8 * 33;              // [32]

    int tok0 = blockIdx.x * 32;
    int tx = threadIdx.x & 31;               // token lane
    int ty = threadIdx.x >> 5;               // 0..7

    float ss = 0.0f;
#pragma unroll 16
    for (int i = 0; i < 64; i++) {
        int c = ty + 8 * i;
        float v = x[(size_t)c * NTOK + tok0 + tx];
        t[c * 33 + tx] = v;
        ss += v * v;
    }
    red[ty * 33 + tx] = ss;
    __syncthreads();
    if (ty == 0) {
        float tot = 0.0f;
#pragma unroll
        for (int j = 0; j < 8; j++) tot += red[j * 33 + tx];
        rsh[tx] = rsqrtf(tot * (1.0f / (float)C_DIM) + EPSF);
    }
    __syncthreads();

#pragma unroll 4
    for (int cc = 0; cc < 16; cc++) {
        int c = cc * 32 + tx;
        float sc = g_s[c];
#pragma unroll
        for (int rr = 0; rr < 4; rr++) {
            int row = ty * 4 + rr;
            g_xn[(size_t)(tok0 + row) * C_DIM + c] = t[c * 33 + row] * sc * rsh[row];
        }
    }
}

// ---------------- tf32 tensor-core GEMM, cp.async 3-stage pipeline -----------
__device__ __forceinline__ void cp16(uint32_t dst, const void* src) {
    asm volatile("cp.async.ca.shared.global [%0], [%1], 16;\n"
                 :: "r"(dst), "l"(src));
}
__device__ __forceinline__ void cp_commit() {
    asm volatile("cp.async.commit_group;\n" ::: "memory");
}
__device__ __forceinline__ void cp_wait1() {
    asm volatile("cp.async.wait_group 1;\n" ::: "memory");
}
__device__ __forceinline__ void cp_wait0() {
    asm volatile("cp.async.wait_group 0;\n" ::: "memory");
}

template <int EPI>
__global__ __launch_bounds__(256, 2) void nsab_mma_gemm(
    const float* __restrict__ A, const float* __restrict__ B,
    float* __restrict__ Cmat, const float* __restrict__ skip,
    int M, int N, int K) {
    extern __shared__ uint32_t sm[];

    const int tid = threadIdx.x;
    const int brow = blockIdx.y * 128;
    const int bcol = blockIdx.x * 128;

    const int warp = tid >> 5;
    const int lane = tid & 31;
    const int m_warp = (warp >> 2) * 64;
    const int n_warp = (warp & 3) * 32;
    const int r = lane >> 2;            // 0..7
    const int c = lane & 3;             // 0..3

    const int a_row = tid >> 3, a_q = tid & 7;
    const int b_k = tid >> 5, b_q = tid & 31;
    uint32_t smem_base;
    {
        void* p = (void*)sm;
        smem_base = (uint32_t)__cvta_generic_to_shared(p);
    }

    float acc[4][4][4];
#pragma unroll
    for (int mt = 0; mt < 4; mt++)
#pragma unroll
        for (int nt = 0; nt < 4; nt++)
#pragma unroll
            for (int i = 0; i < 4; i++) acc[mt][nt][i] = 0.0f;

    const int KT = K >> 5;

    auto issue = [&](int kt, int s) {
        uint32_t sA = smem_base + (uint32_t)(s * STG_WORDS) * 4u;
        uint32_t sB = sA + A_WORDS * 4u;
#pragma unroll
        for (int i = 0; i < 4; i++) {
            int row = a_row + 32 * i;
            cp16(sA + (uint32_t)(row * AP + a_q * 4) * 4u,
                 A + (size_t)(brow + row) * K + kt * BK + a_q * 4);
        }
#pragma unroll
        for (int i = 0; i < 4; i++) {
            int k = b_k + 8 * i;
            cp16(sB + (uint32_t)(k * BP + b_q * 4) * 4u,
                 B + (size_t)(kt * BK + k) * N + bcol + b_q * 4);
        }
        cp_commit();
    };

    issue(0, 0);
    if (KT > 1) issue(1, 1);

    int stage = 0;
    for (int kt = 0; kt < KT; kt++) {
        if (kt + 1 < KT) cp_wait1(); else cp_wait0();
        __syncthreads();
        if (kt + 2 < KT) {
            int ns = stage + 2; if (ns >= NSTAGE) ns -= NSTAGE;
            issue(kt + 2, ns);
        }

        const uint32_t* Asu = sm + stage * STG_WORDS;
        const uint32_t* Bsu = Asu + A_WORDS;

#pragma unroll
        for (int j = 0; j < 4; j++) {
            uint32_t a[4][4];
#pragma unroll
            for (int mt = 0; mt < 4; mt++) {
                const uint32_t* p0 = Asu + (m_warp + mt * 16 + r) * AP + j * 8 + c;
                a[mt][0] = p0[0];
                a[mt][2] = p0[4];
                a[mt][1] = p0[8 * AP];
                a[mt][3] = p0[8 * AP + 4];
            }
            uint32_t b0[4], b1[4];
#pragma unroll
            for (int nt = 0; nt < 4; nt++) {
                const uint32_t* q0 = Bsu + (j * 8 + c) * BP + n_warp + nt * 8 + r;
                b0[nt] = q0[0];
                b1[nt] = q0[4 * BP];
            }
#pragma unroll
            for (int mt = 0; mt < 4; mt++)
#pragma unroll
                for (int nt = 0; nt < 4; nt++) {
                    asm volatile(
                        "mma.sync.aligned.m16n8k8.row.col.f32.tf32.tf32.f32 "
                        "{%0,%1,%2,%3}, {%4,%5,%6,%7}, {%8,%9}, {%0,%1,%2,%3};"
                        : "+f"(acc[mt][nt][0]), "+f"(acc[mt][nt][1]),
                          "+f"(acc[mt][nt][2]), "+f"(acc[mt][nt][3])
                        : "r"(a[mt][0]), "r"(a[mt][1]),
                          "r"(a[mt][2]), "r"(a[mt][3]),
                          "r"(b0[nt]), "r"(b1[nt]));
                }
        }

        stage++; if (stage >= NSTAGE) stage -= NSTAGE;
    }

#pragma unroll
    for (int mt = 0; mt < 4; mt++) {
        int row = brow + m_warp + mt * 16 + r;
#pragma unroll
        for (int nt = 0; nt < 4; nt++) {
            int col = bcol + n_warp + nt * 8 + 2 * c;
            if (EPI == 0) {
                float2 v0 = make_float2(acc[mt][nt][0], acc[mt][nt][1]);
                float2 v1 = make_float2(acc[mt][nt][2], acc[mt][nt][3]);
                *(float2*)&Cmat[(size_t)row * N + col] = v0;
                *(float2*)&Cmat[(size_t)(row + 8) * N + col] = v1;
            } else {
                size_t i00 = (size_t)col * M + row;
                size_t i01 = (size_t)(col + 1) * M + row;
                Cmat[i00] = acc[mt][nt][0] + skip[i00];
                Cmat[i01] = acc[mt][nt][1] + skip[i01];
                Cmat[i00 + 8] = acc[mt][nt][2] + skip[i00 + 8];
                Cmat[i01 + 8] = acc[mt][nt][3] + skip[i01 + 8];
            }
        }
    }
}

// ---------------- QK L2-norm + RoPE: one block per token, shuffle-only -------
__global__ __launch_bounds__(256) void nsab_rope_kernel(
    const float* __restrict__ pos, const float* __restrict__ scale) {
    int tok = blockIdx.x;
    int head = threadIdx.x >> 5;
    int lane = threadIdx.x & 31;
    int hw = tok & 1023;
    float px = pos[hw * 2 + 0];
    float py = pos[hw * 2 + 1];

    float* qp = &g_qkv[(size_t)tok * 1536 + head * 64 + lane];
    float* kp = qp + 512;
    float q0 = qp[0], q1 = qp[32];
    float k0 = kp[0], k1 = kp[32];

    float sq = q0 * q0 + q1 * q1;
    float sk = k0 * k0 + k1 * k1;
#pragma unroll
    for (int o = 16; o; o >>= 1) {
        sq += __shfl_xor_sync(0xFFFFFFFFu, sq, o);
        sk += __shfl_xor_sync(0xFFFFFFFFu, sk, o);
    }
    float ssc = sqrtf(scale[head]);
    float qn = ssc * rsqrtf(sq + EPSF);
    float kn = ssc * rsqrtf(sk + EPSF);
    q0 *= qn; q1 *= qn;
    k0 *= kn; k1 *= kn;

    int i = lane & 15;
    int idx = (i & 7) * 8 + head;
    float freq = expf(1.1447298858494002f + (float)idx * 0.03597789207803891f);
    float th = ((i < 8) ? px : py) * freq;
    float ct = cosf(th), st = sinf(th);

    float qpart = __shfl_xor_sync(0xFFFFFFFFu, q0, 16);
    float kpart = __shfl_xor_sync(0xFFFFFFFFu, k0, 16);
    float qo, ko;
    if (lane < 16) { qo = q0 * ct - qpart * st; ko = k0 * ct - kpart * st; }
    else           { qo = q0 * ct + qpart * st; ko = k0 * ct + kpart * st; }

    qp[0] = qo;  qp[32] = q1;
    kp[0] = ko;  kp[32] = k1;
}

// ---------------- tiled 7x7 neighborhood attention ---------------------------
// one block = 4x8 token tile x (n, head); K/V window union (<=10x14) in smem.
__global__ __launch_bounds__(512) void nsab_attn_kernel() {
    extern __shared__ float sma[];
    float* sk = sma;                                   // [140][KVSTRIDE]
    float* sv = sk + KVROWS * KVSTRIDE;                // [140][KVSTRIDE]
    float* sq = sv + KVROWS * KVSTRIDE;                // [32][KVSTRIDE]
    float* sl = sq + NTOK_T * KVSTRIDE;                // [32][52]
    float* pinv = sl + NTOK_T * 52;                    // [32]

    int tid = threadIdx.x;
    int th = blockIdx.x >> 2, tw = blockIdx.x & 3;
    int head = blockIdx.y;
    int n = blockIdx.z;
    int h1 = th * ATH, w1 = tw * ATW;

    int h0min = min(max(h1 - 3, 0), HH - KSZ);
    int w0min = min(max(w1 - 3, 0), WWID - KSZ);
    int h0max = min(max(h1 + ATH - 1 - 3, 0), HH - KSZ);
    int w0max = min(max(w1 + ATW - 1 - 3, 0), WWID - KSZ);
    int span_h = h0max - h0min + KSZ;    // <= 10
    int span_w = w0max - w0min + KSZ;    // <= 14

    // ---- stage K, V window union ----
    int total = span_h * span_w * 16;    // float4 chunks per matrix
    for (int idxi = tid; idxi < total; idxi += 512) {
        int kpos = idxi >> 4, f = idxi & 15;
        int kr = kpos / span_w, kc = kpos - kr * span_w;
        size_t gbase = (size_t)((n << 10) + (h0min + kr) * 32 + (w0min + kc)) * 1536
                       + head * 64 + f * 4;
        float4 kvv = *(const float4*)&g_qkv[gbase + 512];
        float4 vvv = *(const float4*)&g_qkv[gbase + 1024];
        *(float4*)&sk[kpos * KVSTRIDE + f * 4] = kvv;
        *(float4*)&sv[kpos * KVSTRIDE + f * 4] = vvv;
    }
    // ---- stage q for 32 tokens (512 threads exactly cover 32x16 chunks) ----
    {
        int tl = tid >> 4, f = tid & 15;
        int hh = h1 + (tl >> 3), ww = w1 + (tl & 7);
        size_t gbase = (size_t)((n << 10) + hh * 32 + ww) * 1536 + head * 64 + f * 4;
        *(float4*)&sq[tl * KVSTRIDE + f * 4] = *(const float4*)&g_qkv[gbase];
    }
    __syncthreads();

    // ---- logits: 32 tokens x 49 window positions (4-chain accumulator) ----
    for (int it = tid; it < NTOK_T * WIN; it += 512) {
        int tl = it / WIN, wp = it - tl * WIN;
        int hh = h1 + (tl >> 3), ww = w1 + (tl & 7);
        int dh0 = min(max(hh - 3, 0), HH - KSZ) - h0min;
        int dw0 = min(max(ww - 3, 0), WWID - KSZ) - w0min;
        int kr = wp / KSZ, kc = wp - kr * KSZ;
        const float4* kv = (const float4*)&sk[((dh0 + kr) * span_w + dw0 + kc) * KVSTRIDE];
        const float4* qv = (const float4*)&sq[tl * KVSTRIDE];
        float4 a4 = make_float4(0.f, 0.f, 0.f, 0.f);
#pragma unroll
        for (int i = 0; i < 16; i++) {
            float4 a = kv[i], b = qv[i];
            a4.x += a.x * b.x; a4.y += a.y * b.y;
            a4.z += a.z * b.z; a4.w += a.w * b.w;
        }
        sl[tl * 52 + wp] = (a4.x + a4.y) + (a4.z + a4.w);
    }
    __syncthreads();

    // ---- softmax per token (32 threads) ----
    if (tid < NTOK_T) {
        float mx = -1e30f;
#pragma unroll
        for (int j = 0; j < WIN; j++) mx = fmaxf(mx, sl[tid * 52 + j]);
        float den = 0.0f;
#pragma unroll
        for (int j = 0; j < WIN; j++) {
            float e = __expf(sl[tid * 52 + j] - mx);
            sl[tid * 52 + j] = e;
            den += e;
        }
        pinv[tid] = 1.0f / den;
    }
    __syncthreads();

    // ---- output: 32 tokens x 64 channels (2-chain accumulator) ----
    for (int idxo = tid; idxo < NTOK_T * 64; idxo += 512) {
        int tl = idxo >> 6, e = idxo & 63;
        int hh = h1 + (tl >> 3), ww = w1 + (tl & 7);
        int dh0 = min(max(hh - 3, 0), HH - KSZ) - h0min;
        int dw0 = min(max(ww - 3, 0), WWID - KSZ) - w0min;
        float acc0 = 0.0f, acc1 = 0.0f;
        const float* slp = &sl[tl * 52];
#pragma unroll
        for (int kr = 0; kr < KSZ; kr++) {
            int base = (dh0 + kr) * span_w + dw0;
#pragma unroll
            for (int kc = 0; kc < KSZ; kc += 2)
                acc0 += slp[kr * KSZ + kc] * sv[(base + kc) * KVSTRIDE + e];
#pragma unroll
            for (int kc = 1; kc < KSZ; kc += 2)
                acc1 += slp[kr * KSZ + kc] * sv[(base + kc) * KVSTRIDE + e];
        }
        g_o[(size_t)((n << 10) + hh * 32 + ww) * 512 + head * 64 + e] =
            (acc0 + acc1) * pinv[tl];
    }
}

// ---------------- launch ------------------------------------------------------
extern "C" void kernel_launch(void* const* d_in, const int* in_sizes, int n_in,
                              void* d_out, int out_size) {
    const float* x      = (const float*)d_in[0];
    const float* pos    = (const float*)d_in[1];
    const float* cond   = (const float*)d_in[2];
    const float* norm_w = (const float*)d_in[3];
    const float* qkv_w  = (const float*)d_in[4];
    const float* scale  = (const float*)d_in[5];
    const float* out_w  = (const float*)d_in[6];
    float* out = (float*)d_out;

    float *p_xn, *p_qkv, *p_o;
    cudaGetSymbolAddress((void**)&p_xn,  g_xn);
    cudaGetSymbolAddress((void**)&p_qkv, g_qkv);
    cudaGetSymbolAddress((void**)&p_o,   g_o);

    cudaFuncSetAttribute(nsab_mma_gemm<0>,
                         cudaFuncAttributeMaxDynamicSharedMemorySize, GEMM_SMEM);
    cudaFuncSetAttribute(nsab_mma_gemm<1>,
                         cudaFuncAttributeMaxDynamicSharedMemorySize, GEMM_SMEM);
    cudaFuncSetAttribute(nsab_attn_kernel,
                         cudaFuncAttributeMaxDynamicSharedMemorySize, ATTN_SMEM);
    cudaFuncSetAttribute(nsab_norm_fused,
                         cudaFuncAttributeMaxDynamicSharedMemorySize, NORM_SMEM);

    nsab_s_kernel<<<2, 256>>>(cond, norm_w);
    nsab_norm_fused<<<NTOK / 32, 256, NORM_SMEM>>>(x);
    nsab_mma_gemm<0><<<dim3(3 * C_DIM / 128, NTOK / 128), 256, GEMM_SMEM>>>(
        p_xn, qkv_w, p_qkv, nullptr, NTOK, 3 * C_DIM, C_DIM);
    nsab_rope_kernel<<<NTOK, 256>>>(pos, scale);
    nsab_attn_kernel<<<dim3(32, NH, 4), 512, ATTN_SMEM>>>();
    nsab_mma_gemm<1><<<dim3(C_DIM / 128, NTOK / 128), 256, GEMM_SMEM>>>(
        p_o, out_w, out, x, NTOK, C_DIM, C_DIM);
}

// round 12
// speedup vs baseline: 1.1448x; 1.1448x over previous
#include <cuda_runtime.h>
#include <math.h>
#include <stdint.h>

#define C_DIM 512
#define CF    256      // cond features
#define NH    8
#define DH    64
#define NTOK  4096     // N*H*W = 4*32*32
#define HH    32
#define WWID  32
#define KSZ   7
#define WIN   49
#define EPSF  1e-6f

// GEMM tiling
#define BK        32
#define AP        36            // A smem row stride (words): bank = 4r+c, conflict-free
#define BP        136           // B smem k-row stride (words): bank = 8c+r, conflict-free
#define A_WORDS   (128 * AP)    // 4608
#define B_WORDS   (BK * BP)     // 4352
#define STG_WORDS (A_WORDS + B_WORDS)
#define NSTAGE    3
#define GEMM_SMEM (NSTAGE * STG_WORDS * 4)   // 107520 bytes

// attention: 4x4 token tile, union <= 10x10 = 100 positions, padded to 104
#define NPOS      104
#define NPT       13            // n-tiles of 8 positions
#define KVS       68            // K/V/q smem row stride (words)
#define PSTRIDE   108           // P/L smem row stride (words)
#define SQ_OFF    0                              // sq  [16][68]
#define SK_OFF    (16 * KVS)                     // sk  [104][68]
#define SV_OFF    (SK_OFF + NPOS * KVS)          // sv  [104][68]
#define PSL_OFF   (SV_OFF + NPOS * KVS)          // psl [16][108]
#define PINV_OFF  (PSL_OFF + 16 * PSTRIDE)       // pinv[16]
#define ATTN_SMEM ((PINV_OFF + 16) * 4)          // ~67.9 KB

// fused norm smem: x tile [512][33] + reductions
#define NORM_SMEM ((C_DIM * 33 + 8 * 33 + 32) * 4)

// ---------------- scratch (static device globals; no allocations) ------------
__device__ float g_s[C_DIM];
__device__ float g_xn[NTOK * C_DIM];          // 8 MB
__device__ float g_qkv[NTOK * 3 * C_DIM];     // 24 MB  (q|k|v each 512 cols)
__device__ float g_o[NTOK * C_DIM];           // 8 MB

// ---------------- s = cond @ norm_w + 1 --------------------------------------
__global__ void nsab_s_kernel(const float* __restrict__ cond,
                              const float* __restrict__ norm_w) {
    int c = blockIdx.x * blockDim.x + threadIdx.x;
    if (c >= C_DIM) return;
    float acc = 1.0f;
#pragma unroll 8
    for (int k = 0; k < CF; k++) acc += cond[k] * norm_w[k * C_DIM + c];
    g_s[c] = acc;
}

// ---------------- fused RMS-norm + transpose (C,tok)->(tok,C) ----------------
__global__ __launch_bounds__(256) void nsab_norm_fused(const float* __restrict__ x) {
    extern __shared__ float smf[];
    float* t    = smf;                       // [512][33]
    float* red  = smf + C_DIM * 33;          // [8][33]
    float* rsh  = red + 8 * 33;              // [32]

    int tok0 = blockIdx.x * 32;
    int tx = threadIdx.x & 31;               // token lane
    int ty = threadIdx.x >> 5;               // 0..7

    float ss = 0.0f;
#pragma unroll 16
    for (int i = 0; i < 64; i++) {
        int c = ty + 8 * i;
        float v = x[(size_t)c * NTOK + tok0 + tx];
        t[c * 33 + tx] = v;
        ss += v * v;
    }
    red[ty * 33 + tx] = ss;
    __syncthreads();
    if (ty == 0) {
        float tot = 0.0f;
#pragma unroll
        for (int j = 0; j < 8; j++) tot += red[j * 33 + tx];
        rsh[tx] = rsqrtf(tot * (1.0f / (float)C_DIM) + EPSF);
    }
    __syncthreads();

#pragma unroll 4
    for (int cc = 0; cc < 16; cc++) {
        int c = cc * 32 + tx;
        float sc = g_s[c];
#pragma unroll
        for (int rr = 0; rr < 4; rr++) {
            int row = ty * 4 + rr;
            g_xn[(size_t)(tok0 + row) * C_DIM + c] = t[c * 33 + row] * sc * rsh[row];
        }
    }
}

// ---------------- tf32 tensor-core GEMM, cp.async 3-stage pipeline -----------
__device__ __forceinline__ void cp16(uint32_t dst, const void* src) {
    asm volatile("cp.async.ca.shared.global [%0], [%1], 16;\n"
                 :: "r"(dst), "l"(src));
}
__device__ __forceinline__ void cp_commit() {
    asm volatile("cp.async.commit_group;\n" ::: "memory");
}
__device__ __forceinline__ void cp_wait1() {
    asm volatile("cp.async.wait_group 1;\n" ::: "memory");
}
__device__ __forceinline__ void cp_wait0() {
    asm volatile("cp.async.wait_group 0;\n" ::: "memory");
}
__device__ __forceinline__ void mma_tf32(float& d0, float& d1, float& d2, float& d3,
                                         uint32_t a0, uint32_t a1, uint32_t a2, uint32_t a3,
                                         uint32_t b0, uint32_t b1) {
    asm volatile(
        "mma.sync.aligned.m16n8k8.row.col.f32.tf32.tf32.f32 "
        "{%0,%1,%2,%3}, {%4,%5,%6,%7}, {%8,%9}, {%0,%1,%2,%3};"
        : "+f"(d0), "+f"(d1), "+f"(d2), "+f"(d3)
        : "r"(a0), "r"(a1), "r"(a2), "r"(a3), "r"(b0), "r"(b1));
}

template <int EPI>
__global__ __launch_bounds__(256, 2) void nsab_mma_gemm(
    const float* __restrict__ A, const float* __restrict__ B,
    float* __restrict__ Cmat, const float* __restrict__ skip,
    int M, int N, int K) {
    extern __shared__ uint32_t sm[];

    const int tid = threadIdx.x;
    const int brow = blockIdx.y * 128;
    const int bcol = blockIdx.x * 128;

    const int warp = tid >> 5;
    const int lane = tid & 31;
    const int m_warp = (warp >> 2) * 64;
    const int n_warp = (warp & 3) * 32;
    const int r = lane >> 2;            // 0..7
    const int c = lane & 3;             // 0..3

    const int a_row = tid >> 3, a_q = tid & 7;
    const int b_k = tid >> 5, b_q = tid & 31;
    uint32_t smem_base;
    {
        void* p = (void*)sm;
        smem_base = (uint32_t)__cvta_generic_to_shared(p);
    }

    float acc[4][4][4];
#pragma unroll
    for (int mt = 0; mt < 4; mt++)
#pragma unroll
        for (int nt = 0; nt < 4; nt++)
#pragma unroll
            for (int i = 0; i < 4; i++) acc[mt][nt][i] = 0.0f;

    const int KT = K >> 5;

    auto issue = [&](int kt, int s) {
        uint32_t sA = smem_base + (uint32_t)(s * STG_WORDS) * 4u;
        uint32_t sB = sA + A_WORDS * 4u;
#pragma unroll
        for (int i = 0; i < 4; i++) {
            int row = a_row + 32 * i;
            cp16(sA + (uint32_t)(row * AP + a_q * 4) * 4u,
                 A + (size_t)(brow + row) * K + kt * BK + a_q * 4);
        }
#pragma unroll
        for (int i = 0; i < 4; i++) {
            int k = b_k + 8 * i;
            cp16(sB + (uint32_t)(k * BP + b_q * 4) * 4u,
                 B + (size_t)(kt * BK + k) * N + bcol + b_q * 4);
        }
        cp_commit();
    };

    issue(0, 0);
    if (KT > 1) issue(1, 1);

    int stage = 0;
    for (int kt = 0; kt < KT; kt++) {
        if (kt + 1 < KT) cp_wait1(); else cp_wait0();
        __syncthreads();
        if (kt + 2 < KT) {
            int ns = stage + 2; if (ns >= NSTAGE) ns -= NSTAGE;
            issue(kt + 2, ns);
        }

        const uint32_t* Asu = sm + stage * STG_WORDS;
        const uint32_t* Bsu = Asu + A_WORDS;

#pragma unroll
        for (int j = 0; j < 4; j++) {
            uint32_t a[4][4];
#pragma unroll
            for (int mt = 0; mt < 4; mt++) {
                const uint32_t* p0 = Asu + (m_warp + mt * 16 + r) * AP + j * 8 + c;
                a[mt][0] = p0[0];
                a[mt][2] = p0[4];
                a[mt][1] = p0[8 * AP];
                a[mt][3] = p0[8 * AP + 4];
            }
            uint32_t b0[4], b1[4];
#pragma unroll
            for (int nt = 0; nt < 4; nt++) {
                const uint32_t* q0 = Bsu + (j * 8 + c) * BP + n_warp + nt * 8 + r;
                b0[nt] = q0[0];
                b1[nt] = q0[4 * BP];
            }
#pragma unroll
            for (int mt = 0; mt < 4; mt++)
#pragma unroll
                for (int nt = 0; nt < 4; nt++) {
                    mma_tf32(acc[mt][nt][0], acc[mt][nt][1],
                             acc[mt][nt][2], acc[mt][nt][3],
                             a[mt][0], a[mt][1], a[mt][2], a[mt][3],
                             b0[nt], b1[nt]);
                }
        }

        stage++; if (stage >= NSTAGE) stage -= NSTAGE;
    }

#pragma unroll
    for (int mt = 0; mt < 4; mt++) {
        int row = brow + m_warp + mt * 16 + r;
#pragma unroll
        for (int nt = 0; nt < 4; nt++) {
            int col = bcol + n_warp + nt * 8 + 2 * c;
            if (EPI == 0) {
                float2 v0 = make_float2(acc[mt][nt][0], acc[mt][nt][1]);
                float2 v1 = make_float2(acc[mt][nt][2], acc[mt][nt][3]);
                *(float2*)&Cmat[(size_t)row * N + col] = v0;
                *(float2*)&Cmat[(size_t)(row + 8) * N + col] = v1;
            } else {
                size_t i00 = (size_t)col * M + row;
                size_t i01 = (size_t)(col + 1) * M + row;
                Cmat[i00] = acc[mt][nt][0] + skip[i00];
                Cmat[i01] = acc[mt][nt][1] + skip[i01];
                Cmat[i00 + 8] = acc[mt][nt][2] + skip[i00 + 8];
                Cmat[i01 + 8] = acc[mt][nt][3] + skip[i01 + 8];
            }
        }
    }
}

// ---------------- QK L2-norm + RoPE: one block per token, shuffle-only -------
__global__ __launch_bounds__(256) void nsab_rope_kernel(
    const float* __restrict__ pos, const float* __restrict__ scale) {
    int tok = blockIdx.x;
    int head = threadIdx.x >> 5;
    int lane = threadIdx.x & 31;
    int hw = tok & 1023;
    float px = pos[hw * 2 + 0];
    float py = pos[hw * 2 + 1];

    float* qp = &g_qkv[(size_t)tok * 1536 + head * 64 + lane];
    float* kp = qp + 512;
    float q0 = qp[0], q1 = qp[32];
    float k0 = kp[0], k1 = kp[32];

    float sq = q0 * q0 + q1 * q1;
    float sk = k0 * k0 + k1 * k1;
#pragma unroll
    for (int o = 16; o; o >>= 1) {
        sq += __shfl_xor_sync(0xFFFFFFFFu, sq, o);
        sk += __shfl_xor_sync(0xFFFFFFFFu, sk, o);
    }
    float ssc = sqrtf(scale[head]);
    float qn = ssc * rsqrtf(sq + EPSF);
    float kn = ssc * rsqrtf(sk + EPSF);
    q0 *= qn; q1 *= qn;
    k0 *= kn; k1 *= kn;

    int i = lane & 15;
    int idx = (i & 7) * 8 + head;
    float freq = expf(1.1447298858494002f + (float)idx * 0.03597789207803891f);
    float th = ((i < 8) ? px : py) * freq;
    float ct = cosf(th), st = sinf(th);

    float qpart = __shfl_xor_sync(0xFFFFFFFFu, q0, 16);
    float kpart = __shfl_xor_sync(0xFFFFFFFFu, k0, 16);
    float qo, ko;
    if (lane < 16) { qo = q0 * ct - qpart * st; ko = k0 * ct - kpart * st; }
    else           { qo = q0 * ct + qpart * st; ko = k0 * ct + kpart * st; }

    qp[0] = qo;  qp[32] = q1;
    kp[0] = ko;  kp[32] = k1;
}

// ---------------- tensor-core 7x7 neighborhood attention ---------------------
// one block = 4x4 token tile x (n, head), 256 threads = 8 warps.
// L = Q K^T and O = P V are tf32 mma.sync over the window union (<=100 pos,
// padded to 104 with zero rows); per-token 49-window mask applied at softmax.
__global__ __launch_bounds__(256) void nsab_attn_kernel() {
    extern __shared__ float sma[];
    float* sq   = sma + SQ_OFF;      // [16][KVS]
    float* sk   = sma + SK_OFF;      // [104][KVS]
    float* sv   = sma + SV_OFF;      // [104][KVS]
    float* psl  = sma + PSL_OFF;     // [16][PSTRIDE]  (logits, then P)
    float* pinv = sma + PINV_OFF;    // [16]

    const int tid = threadIdx.x;
    const int warp = tid >> 5;
    const int lane = tid & 31;
    const int r = lane >> 2;         // 0..7
    const int c = lane & 3;          // 0..3

    const int th = blockIdx.x >> 3, tw = blockIdx.x & 7;
    const int head = blockIdx.y;
    const int n = blockIdx.z;
    const int h1 = th * 4, w1 = tw * 4;

    const int h0min = min(max(h1 - 3, 0), HH - KSZ);
    const int w0min = min(max(w1 - 3, 0), WWID - KSZ);
    const int h0max = min(max(h1 + 3 - 3, 0), HH - KSZ);
    const int w0max = min(max(w1 + 3 - 3, 0), WWID - KSZ);
    const int span_h = h0max - h0min + KSZ;  // <= 10
    const int span_w = w0max - w0min + KSZ;  // <= 10
    const int nreal = span_h * span_w;       // <= 100

    // ---- stage K, V ([pos][dim], zero-filled beyond nreal) ----
    for (int idxi = tid; idxi < NPOS * 16; idxi += 256) {
        int kpos = idxi >> 4, f = idxi & 15;
        if (kpos < nreal) {
            int kr = kpos / span_w, kc = kpos - kr * span_w;
            size_t g = (size_t)((n << 10) + (h0min + kr) * 32 + (w0min + kc)) * 1536
                       + head * 64 + f * 4;
            *(float4*)&sk[kpos * KVS + f * 4] = *(const float4*)&g_qkv[g + 512];
            *(float4*)&sv[kpos * KVS + f * 4] = *(const float4*)&g_qkv[g + 1024];
        } else {
            float4 z = make_float4(0.f, 0.f, 0.f, 0.f);
            *(float4*)&sk[kpos * KVS + f * 4] = z;
            *(float4*)&sv[kpos * KVS + f * 4] = z;
        }
    }
    // ---- stage q (16 tokens x 16 float4 = 256 threads) ----
    {
        int tl = tid >> 4, f = tid & 15;
        int hh = h1 + (tl >> 2), ww = w1 + (tl & 3);
        size_t g = (size_t)((n << 10) + hh * 32 + ww) * 1536 + head * 64 + f * 4;
        *(float4*)&sq[tl * KVS + f * 4] = *(const float4*)&g_qkv[g];
    }
    __syncthreads();

    // ---- logits MMA: L[16][104] = Q[16][64] . K[104][64]^T ----
    const uint32_t* squ = (const uint32_t*)sq;
    const uint32_t* sku = (const uint32_t*)sk;
    for (int nt = warp; nt < NPT; nt += 8) {
        float d0 = 0.f, d1 = 0.f, d2 = 0.f, d3 = 0.f;
#pragma unroll
        for (int ks = 0; ks < 8; ks++) {
            uint32_t a0 = squ[r * KVS + ks * 8 + c];
            uint32_t a1 = squ[(r + 8) * KVS + ks * 8 + c];
            uint32_t a2 = squ[r * KVS + ks * 8 + c + 4];
            uint32_t a3 = squ[(r + 8) * KVS + ks * 8 + c + 4];
            uint32_t b0 = sku[(nt * 8 + r) * KVS + ks * 8 + c];
            uint32_t b1 = sku[(nt * 8 + r) * KVS + ks * 8 + c + 4];
            mma_tf32(d0, d1, d2, d3, a0, a1, a2, a3, b0, b1);
        }
        psl[r * PSTRIDE + nt * 8 + 2 * c]           = d0;
        psl[r * PSTRIDE + nt * 8 + 2 * c + 1]       = d1;
        psl[(r + 8) * PSTRIDE + nt * 8 + 2 * c]     = d2;
        psl[(r + 8) * PSTRIDE + nt * 8 + 2 * c + 1] = d3;
    }
    __syncthreads();

    // ---- masked softmax per token; P written in-place, zeros outside window
    if (tid < 16) {
        int hh = h1 + (tid >> 2), ww = w1 + (tid & 3);
        int dh0 = min(max(hh - 3, 0), HH - KSZ) - h0min;
        int dw0 = min(max(ww - 3, 0), WWID - KSZ) - w0min;
        float* row = &psl[tid * PSTRIDE];
        float mx = -1e30f;
#pragma unroll
        for (int kr = 0; kr < KSZ; kr++)
#pragma unroll
            for (int kc = 0; kc < KSZ; kc++)
                mx = fmaxf(mx, row[(dh0 + kr) * span_w + dw0 + kc]);
        float den = 0.0f;
#pragma unroll
        for (int kr = 0; kr < KSZ; kr++)
#pragma unroll
            for (int kc = 0; kc < KSZ; kc++) {
                int j = (dh0 + kr) * span_w + dw0 + kc;
                float e = __expf(row[j] - mx);
                row[j] = e;
                den += e;
            }
        pinv[tid] = 1.0f / den;
        // zero non-window entries (incl. padding)
        for (int kr = 0; kr < span_h; kr++) {
            bool rin = (kr >= dh0) & (kr < dh0 + KSZ);
            for (int kc = 0; kc < span_w; kc++) {
                if (!(rin & (kc >= dw0) & (kc < dw0 + KSZ)))
                    row[kr * span_w + kc] = 0.0f;
            }
        }
        for (int j = nreal; j < NPOS; j++) row[j] = 0.0f;
    }
    __syncthreads();

    // ---- output MMA: O[16][64] = P[16][104] . V[104][64] ----
    {
        const uint32_t* pslu = (const uint32_t*)psl;
        const uint32_t* svu = (const uint32_t*)sv;
        int nt = warp;                // 8 warps x 8-channel tile
        float d0 = 0.f, d1 = 0.f, d2 = 0.f, d3 = 0.f;
#pragma unroll
        for (int ks = 0; ks < NPT; ks++) {
            uint32_t a0 = pslu[r * PSTRIDE + ks * 8 + c];
            uint32_t a1 = pslu[(r + 8) * PSTRIDE + ks * 8 + c];
            uint32_t a2 = pslu[r * PSTRIDE + ks * 8 + c + 4];
            uint32_t a3 = pslu[(r + 8) * PSTRIDE + ks * 8 + c + 4];
            uint32_t b0 = svu[(ks * 8 + c) * KVS + nt * 8 + r];
            uint32_t b1 = svu[(ks * 8 + c + 4) * KVS + nt * 8 + r];
            mma_tf32(d0, d1, d2, d3, a0, a1, a2, a3, b0, b1);
        }
        // store: token r (d0,d1), token r+8 (d2,d3), channels nt*8 + 2c, +1
        int tA = r, tB = r + 8;
        int hhA = h1 + (tA >> 2), wwA = w1 + (tA & 3);
        int hhB = h1 + (tB >> 2), wwB = w1 + (tB & 3);
        float iA = pinv[tA], iB = pinv[tB];
        size_t gA = (size_t)((n << 10) + hhA * 32 + wwA) * 512 + head * 64 + nt * 8 + 2 * c;
        size_t gB = (size_t)((n << 10) + hhB * 32 + wwB) * 512 + head * 64 + nt * 8 + 2 * c;
        *(float2*)&g_o[gA] = make_float2(d0 * iA, d1 * iA);
        *(float2*)&g_o[gB] = make_float2(d2 * iB, d3 * iB);
    }
}

// ---------------- launch ------------------------------------------------------
extern "C" void kernel_launch(void* const* d_in, const int* in_sizes, int n_in,
                              void* d_out, int out_size) {
    const float* x      = (const float*)d_in[0];
    const float* pos    = (const float*)d_in[1];
    const float* cond   = (const float*)d_in[2];
    const float* norm_w = (const float*)d_in[3];
    const float* qkv_w  = (const float*)d_in[4];
    const float* scale  = (const float*)d_in[5];
    const float* out_w  = (const float*)d_in[6];
    float* out = (float*)d_out;

    float *p_xn, *p_qkv, *p_o;
    cudaGetSymbolAddress((void**)&p_xn,  g_xn);
    cudaGetSymbolAddress((void**)&p_qkv, g_qkv);
    cudaGetSymbolAddress((void**)&p_o,   g_o);

    cudaFuncSetAttribute(nsab_mma_gemm<0>,
                         cudaFuncAttributeMaxDynamicSharedMemorySize, GEMM_SMEM);
    cudaFuncSetAttribute(nsab_mma_gemm<1>,
                         cudaFuncAttributeMaxDynamicSharedMemorySize, GEMM_SMEM);
    cudaFuncSetAttribute(nsab_attn_kernel,
                         cudaFuncAttributeMaxDynamicSharedMemorySize, ATTN_SMEM);
    cudaFuncSetAttribute(nsab_norm_fused,
                         cudaFuncAttributeMaxDynamicSharedMemorySize, NORM_SMEM);

    nsab_s_kernel<<<2, 256>>>(cond, norm_w);
    nsab_norm_fused<<<NTOK / 32, 256, NORM_SMEM>>>(x);
    nsab_mma_gemm<0><<<dim3(3 * C_DIM / 128, NTOK / 128), 256, GEMM_SMEM>>>(
        p_xn, qkv_w, p_qkv, nullptr, NTOK, 3 * C_DIM, C_DIM);
    nsab_rope_kernel<<<NTOK, 256>>>(pos, scale);
    nsab_attn_kernel<<<dim3(64, NH, 4), 256, ATTN_SMEM>>>();
    nsab_mma_gemm<1><<<dim3(C_DIM / 128, NTOK / 128), 256, GEMM_SMEM>>>(
        p_o, out_w, out, x, NTOK, C_DIM, C_DIM);
}